// round 12
// baseline (speedup 1.0000x reference)
#include <cuda_runtime.h>
#include <cuda_fp16.h>
#include <math.h>
#include <cstdint>

#define H_DIM 768
#define D_DIM 384
#define L_DIM 128
#define B_MAX 32768

// -------- scratch (module globals; no runtime allocation) --------
__device__ float  g_x2[B_MAX];
__device__ float  g_y2[L_DIM];
__device__ __half g_Ah[(size_t)B_MAX * H_DIM];   // cls in fp16
__device__ __half g_Xh[(size_t)B_MAX * D_DIM];   // x in fp16
__device__ __half g_Wth[(size_t)D_DIM * H_DIM];  // W^T in fp16 [D][H]
__device__ __half g_Yh[(size_t)L_DIM * D_DIM];   // Y in fp16 [L][D]

// ---------------- helpers ----------------
__device__ __forceinline__ uint32_t smem_u32(const void* p) {
    uint32_t a;
    asm("{ .reg .u64 t; cvta.to.shared.u64 t, %1; cvt.u32.u64 %0, t; }" : "=r"(a) : "l"(p));
    return a;
}
__device__ __forceinline__ void cp_async16(uint32_t s, const void* g) {
    asm volatile("cp.async.cg.shared.global [%0], [%1], 16;" :: "r"(s), "l"(g));
}
#define CP_COMMIT asm volatile("cp.async.commit_group;" ::: "memory")
#define CP_WAIT1  asm volatile("cp.async.wait_group 1;" ::: "memory")
#define CP_WAIT0  asm volatile("cp.async.wait_group 0;" ::: "memory")
#define CP_WAIT2  asm volatile("cp.async.wait_group 2;" ::: "memory")

__device__ __forceinline__ void mma_fp16(float* d, const uint32_t* a, const uint32_t* b) {
    asm volatile(
        "mma.sync.aligned.m16n8k16.row.col.f32.f16.f16.f32 "
        "{%0,%1,%2,%3}, {%4,%5,%6,%7}, {%8,%9}, {%0,%1,%2,%3};"
        : "+f"(d[0]), "+f"(d[1]), "+f"(d[2]), "+f"(d[3])
        : "r"(a[0]), "r"(a[1]), "r"(a[2]), "r"(a[3]), "r"(b[0]), "r"(b[1]));
}
__device__ __forceinline__ void ldsm_x4(uint32_t addr, uint32_t& r0, uint32_t& r1,
                                        uint32_t& r2, uint32_t& r3) {
    asm volatile("ldmatrix.sync.aligned.m8n8.x4.shared.b16 {%0,%1,%2,%3}, [%4];"
                 : "=r"(r0), "=r"(r1), "=r"(r2), "=r"(r3) : "r"(addr));
}

#define ASTR 72                             // 64 k-halves + 8 pad (144B rows)

// ========== GEMM1 fused: CTA 128x384 (full N), 16 warps of 64x48 ==========
#define G1_A_HALVES (128 * ASTR)
#define G1_A_BYTES  (G1_A_HALVES * 2)       // 18432
#define G1_B_HALVES (384 * ASTR)
#define G1_STAGE_HALVES (G1_A_HALVES + G1_B_HALVES)
#define G1_STAGE_BYTES  (G1_STAGE_HALVES * 2)   // 73728
#define G1_SMEM     (2 * G1_STAGE_BYTES)        // 147456

__device__ __forceinline__ void g1_stage(uint32_t sstage, const __half* Ag,
                                         const __half* Bg, int tid) {
#pragma unroll
    for (int i = 0; i < 2; ++i) {           // A: 128x64 -> 1024 tasks
        int idx = i * 512 + tid;
        int row = idx >> 3, k8 = idx & 7;
        cp_async16(sstage + (uint32_t)((row * ASTR + k8 * 8) * 2),
                   Ag + (size_t)row * H_DIM + k8 * 8);
    }
#pragma unroll
    for (int i = 0; i < 6; ++i) {           // B: 384x64 -> 3072 tasks
        int idx = i * 512 + tid;
        int row = idx >> 3, k8 = idx & 7;
        cp_async16(sstage + (uint32_t)(G1_A_BYTES + (row * ASTR + k8 * 8) * 2),
                   Bg + (size_t)row * H_DIM + k8 * 8);
    }
}

// one k64 chunk: 4 k16 steps, warp tile 64x48 (4 A-ldsm + 3 B-ldsm + 24 mma)
__device__ __forceinline__ void g1_compute_chunk(uint32_t sA, uint32_t sB,
                                                 int wm, int wn, int lane,
                                                 float acc[4][6][4]) {
    const int il = lane & 7, g = lane >> 3;
#pragma unroll
    for (int s = 0; s < 4; ++s) {
        const int kb = s * 16;
        uint32_t af[4][4], bf[6][2];
        uint32_t aoff = (uint32_t)(((wm + (g & 1) * 8 + il) * ASTR + kb + (g >> 1) * 8) * 2);
#pragma unroll
        for (int mt = 0; mt < 4; ++mt)
            ldsm_x4(sA + aoff + mt * (16 * ASTR * 2),
                    af[mt][0], af[mt][1], af[mt][2], af[mt][3]);
        uint32_t boff = (uint32_t)(((wn + (g >> 1) * 8 + il) * ASTR + kb + (g & 1) * 8) * 2);
#pragma unroll
        for (int np = 0; np < 3; ++np)
            ldsm_x4(sB + boff + np * (16 * ASTR * 2),
                    bf[np * 2][0], bf[np * 2][1], bf[np * 2 + 1][0], bf[np * 2 + 1][1]);
#pragma unroll
        for (int mt = 0; mt < 4; ++mt)
#pragma unroll
            for (int nt = 0; nt < 6; ++nt)
                mma_fp16(acc[mt][nt], af[mt], bf[nt]);
    }
}

__global__ __launch_bounds__(512, 1)
void gemm1_fused(const float* __restrict__ bias, float* __restrict__ X)
{
    extern __shared__ __half smh[];
    const uint32_t sb = smem_u32(smh);
    const int tid = threadIdx.x, lane = tid & 31, warp = tid >> 5;
    const int wm = (warp >> 3) * 64;        // 0 or 64
    const int cw = warp & 7;                // column-warp index
    const int wn = cw * 48;
    const int rowBase = blockIdx.x * 128;

    const __half* Abase = g_Ah + (size_t)rowBase * H_DIM;
    const __half* Bbase = g_Wth;            // full [384, 768]

    float acc[4][6][4];
#pragma unroll
    for (int mt = 0; mt < 4; ++mt)
#pragma unroll
        for (int nt = 0; nt < 6; ++nt)
#pragma unroll
            for (int q = 0; q < 4; ++q) acc[mt][nt][q] = 0.f;

    const int NCH = H_DIM / 64;   // 12
    g1_stage(sb, Abase, Bbase, tid);
    CP_COMMIT;
    g1_stage(sb + G1_STAGE_BYTES, Abase + 64, Bbase + 64, tid);
    CP_COMMIT;

#pragma unroll 1
    for (int c = 0; c < NCH; ++c) {
        if (c == NCH - 1) { CP_WAIT0; } else { CP_WAIT1; }
        __syncthreads();
        const uint32_t sA = sb + (c & 1) * G1_STAGE_BYTES;
        g1_compute_chunk(sA, sA + G1_A_BYTES, wm, wn, lane, acc);
        if (c + 2 < NCH) {
            __syncthreads();
            g1_stage(sb + (c & 1) * G1_STAGE_BYTES,
                     Abase + (c + 2) * 64, Bbase + (c + 2) * 64, tid);
            CP_COMMIT;
        }
    }
    __syncthreads();   // mainloop done; smem free for reduction

    // ---- fused epilogue: bias, row-norm reduce, expmap0 scale, store ----
    float* rowsum = (float*)smh;            // [128][8]
    float* scales = (float*)smh + 128 * 8;  // [128]

#pragma unroll
    for (int mt = 0; mt < 4; ++mt) {
        float p0 = 0.f, p1 = 0.f;
#pragma unroll
        for (int nt = 0; nt < 6; ++nt) {
            int cc = wn + nt * 8 + (lane & 3) * 2;
            float b0 = bias[cc], b1 = bias[cc + 1];
            acc[mt][nt][0] += b0; acc[mt][nt][1] += b1;
            acc[mt][nt][2] += b0; acc[mt][nt][3] += b1;
            p0 = fmaf(acc[mt][nt][0], acc[mt][nt][0],
                 fmaf(acc[mt][nt][1], acc[mt][nt][1], p0));
            p1 = fmaf(acc[mt][nt][2], acc[mt][nt][2],
                 fmaf(acc[mt][nt][3], acc[mt][nt][3], p1));
        }
        p0 += __shfl_xor_sync(0xFFFFFFFFu, p0, 1);
        p0 += __shfl_xor_sync(0xFFFFFFFFu, p0, 2);
        p1 += __shfl_xor_sync(0xFFFFFFFFu, p1, 1);
        p1 += __shfl_xor_sync(0xFFFFFFFFu, p1, 2);
        if ((lane & 3) == 0) {
            int r = wm + mt * 16 + (lane >> 2);
            rowsum[r * 8 + cw] = p0;
            rowsum[(r + 8) * 8 + cw] = p1;
        }
    }
    __syncthreads();

    if (tid < 128) {
        const float* rs = rowsum + tid * 8;
        float nsq = ((rs[0] + rs[1]) + (rs[2] + rs[3]))
                  + ((rs[4] + rs[5]) + (rs[6] + rs[7]));
        float n = fmaxf(sqrtf(nsq), 1e-15f);
        float scale = tanhf(n) / n;
        scales[tid] = scale;
        g_x2[rowBase + tid] = nsq * scale * scale;
    }
    __syncthreads();

#pragma unroll
    for (int mt = 0; mt < 4; ++mt) {
        int rl = wm + mt * 16 + (lane >> 2);
        int r0 = rowBase + rl;
        float s0 = scales[rl], s1 = scales[rl + 8];
#pragma unroll
        for (int nt = 0; nt < 6; ++nt) {
            int cc = wn + nt * 8 + (lane & 3) * 2;
            float v0 = acc[mt][nt][0] * s0, v1 = acc[mt][nt][1] * s0;
            float v2 = acc[mt][nt][2] * s1, v3 = acc[mt][nt][3] * s1;
            *(float2*)&X[(size_t)r0 * D_DIM + cc]       = make_float2(v0, v1);
            *(float2*)&X[(size_t)(r0 + 8) * D_DIM + cc] = make_float2(v2, v3);
            __half2 h0 = __floats2half2_rn(v0, v1);
            __half2 h1 = __floats2half2_rn(v2, v3);
            *(uint32_t*)&g_Xh[(size_t)r0 * D_DIM + cc]       = *(uint32_t*)&h0;
            *(uint32_t*)&g_Xh[(size_t)(r0 + 8) * D_DIM + cc] = *(uint32_t*)&h1;
        }
    }
}

// ========== GEMM2 (unchanged): 128x128 tile, warp 64x32, fused distance =====
#define A_HALVES (128 * ASTR)
#define A_BYTES  (A_HALVES * 2)
#define STAGE_HALVES (A_HALVES + 128 * ASTR)
#define STAGE_BYTES  (STAGE_HALVES * 2)
#define NSTAGE 3
#define G2_SMEM   (NSTAGE * STAGE_BYTES)

__device__ __forceinline__ void stage_k64(uint32_t sstage, const __half* Ag,
                                          const __half* Bg, int ld, int tid) {
#pragma unroll
    for (int i = 0; i < 4; ++i) {
        int idx = i * 256 + tid;
        int row = idx >> 3, k8 = idx & 7;
        cp_async16(sstage + (uint32_t)((row * ASTR + k8 * 8) * 2),
                   Ag + (size_t)row * ld + k8 * 8);
    }
#pragma unroll
    for (int i = 0; i < 4; ++i) {
        int idx = i * 256 + tid;
        int row = idx >> 3, k8 = idx & 7;
        cp_async16(sstage + (uint32_t)(A_BYTES + (row * ASTR + k8 * 8) * 2),
                   Bg + (size_t)row * ld + k8 * 8);
    }
}

__device__ __forceinline__ void load_frags(uint32_t sA, uint32_t sB, int kb,
                                           int wm, int wn, int lane,
                                           uint32_t af[4][4], uint32_t bf[4][2]) {
    const int il = lane & 7, g = lane >> 3;
    uint32_t aoff = (uint32_t)(((wm + (g & 1) * 8 + il) * ASTR + kb + (g >> 1) * 8) * 2);
#pragma unroll
    for (int mt = 0; mt < 4; ++mt)
        ldsm_x4(sA + aoff + mt * (16 * ASTR * 2),
                af[mt][0], af[mt][1], af[mt][2], af[mt][3]);
    uint32_t boff = (uint32_t)(((wn + (g >> 1) * 8 + il) * ASTR + kb + (g & 1) * 8) * 2);
#pragma unroll
    for (int np = 0; np < 2; ++np)
        ldsm_x4(sB + boff + np * (16 * ASTR * 2),
                bf[np * 2][0], bf[np * 2][1], bf[np * 2 + 1][0], bf[np * 2 + 1][1]);
}
__device__ __forceinline__ void mma_all(uint32_t af[4][4], uint32_t bf[4][2],
                                        float acc[4][4][4]) {
#pragma unroll
    for (int mt = 0; mt < 4; ++mt)
#pragma unroll
        for (int nt = 0; nt < 4; ++nt)
            mma_fp16(acc[mt][nt], af[mt], bf[nt]);
}
__device__ __forceinline__ void compute_chunk(uint32_t sA, uint32_t sB,
                                              int wm, int wn, int lane,
                                              float acc[4][4][4]) {
    uint32_t af[2][4][4], bf[2][4][2];
    load_frags(sA, sB, 0, wm, wn, lane, af[0], bf[0]);
#pragma unroll
    for (int s = 0; s < 4; ++s) {
        if (s < 3)
            load_frags(sA, sB, (s + 1) * 16, wm, wn, lane, af[(s + 1) & 1], bf[(s + 1) & 1]);
        mma_all(af[s & 1], bf[s & 1], acc);
    }
}

// ---------------- conversion kernels ----------------
__global__ void convert_A(const float* __restrict__ A) {
    size_t i = (size_t)blockIdx.x * blockDim.x + threadIdx.x;
    const float4 v0 = ((const float4*)A)[i * 2];
    const float4 v1 = ((const float4*)A)[i * 2 + 1];
    __half2 h0 = __floats2half2_rn(v0.x, v0.y);
    __half2 h1 = __floats2half2_rn(v0.z, v0.w);
    __half2 h2 = __floats2half2_rn(v1.x, v1.y);
    __half2 h3 = __floats2half2_rn(v1.z, v1.w);
    uint4 u;
    u.x = *(uint32_t*)&h0; u.y = *(uint32_t*)&h1;
    u.z = *(uint32_t*)&h2; u.w = *(uint32_t*)&h3;
    ((uint4*)g_Ah)[i] = u;
}

__global__ void transpose_w_h(const float* __restrict__ W) {
    __shared__ float t[32][33];
    int bx = blockIdx.x * 32;
    int by = blockIdx.y * 32;
    int x = threadIdx.x, y = threadIdx.y;
#pragma unroll
    for (int i = 0; i < 32; i += 8)
        t[y + i][x] = W[(size_t)(bx + y + i) * D_DIM + by + x];
    __syncthreads();
#pragma unroll
    for (int i = 0; i < 32; i += 8)
        g_Wth[(size_t)(by + y + i) * H_DIM + bx + x] = __float2half_rn(t[x][y + i]);
}

__global__ __launch_bounds__(256)
void convert_Y(const float* __restrict__ Y) {
    const int warp = threadIdx.x >> 5, lane = threadIdx.x & 31;
    const int row = blockIdx.x * 8 + warp;
    const float* y = Y + (size_t)row * D_DIM;
    __half* yh = g_Yh + (size_t)row * D_DIM;
    float s = 0.f;
#pragma unroll
    for (int j = 0; j < 3; ++j) {
        float4 v = ((const float4*)y)[j * 32 + lane];
        s += v.x * v.x + v.y * v.y + v.z * v.z + v.w * v.w;
        __half2 h0 = __floats2half2_rn(v.x, v.y);
        __half2 h1 = __floats2half2_rn(v.z, v.w);
        uint2 u; u.x = *(uint32_t*)&h0; u.y = *(uint32_t*)&h1;
        ((uint2*)yh)[j * 32 + lane] = u;
    }
#pragma unroll
    for (int o = 16; o > 0; o >>= 1) s += __shfl_xor_sync(0xFFFFFFFFu, s, o);
    if (lane == 0) g_y2[row] = s;
}

// ---------------- GEMM2: xy = x @ Y^T, fused Poincare distance -------------
__global__ __launch_bounds__(256, 2)
void gemm2_mma(float* __restrict__ logits)
{
    extern __shared__ __half smh[];
    const uint32_t sb = smem_u32(smh);
    const int tid = threadIdx.x, lane = tid & 31, warp = tid >> 5;
    const int wm = (warp >> 2) * 64, wn = (warp & 3) * 32;
    const int rowBase = blockIdx.x * 128;

    const __half* Abase = g_Xh + (size_t)rowBase * D_DIM;
    const __half* Bbase = g_Yh;

    float acc[4][4][4];
#pragma unroll
    for (int mt = 0; mt < 4; ++mt)
#pragma unroll
        for (int nt = 0; nt < 4; ++nt)
#pragma unroll
            for (int q = 0; q < 4; ++q) acc[mt][nt][q] = 0.f;

    const int NCH = D_DIM / 64;   // 6
#pragma unroll
    for (int s = 0; s < NSTAGE - 1; ++s) {
        stage_k64(sb + s * STAGE_BYTES, Abase + s * 64, Bbase + s * 64, D_DIM, tid);
        CP_COMMIT;
    }

#pragma unroll 1
    for (int c = 0; c < NCH; ++c) {
        if (c + NSTAGE - 1 < NCH) {
            stage_k64(sb + ((c + NSTAGE - 1) % NSTAGE) * STAGE_BYTES,
                      Abase + (c + NSTAGE - 1) * 64, Bbase + (c + NSTAGE - 1) * 64,
                      D_DIM, tid);
        }
        CP_COMMIT;
        CP_WAIT2;
        __syncthreads();
        const uint32_t sA = sb + (c % NSTAGE) * STAGE_BYTES;
        compute_chunk(sA, sA + A_BYTES, wm, wn, lane, acc);
        __syncthreads();
    }

    const float CLIPMAX = (1.0f - 1e-5f) * (1.0f - 1e-5f);
    const float sclip = sqrtf(CLIPMAX);
    const float dclip = -__logf(__fdividef(1.0f + sclip, 1.0f - sclip));

#pragma unroll
    for (int mt = 0; mt < 4; ++mt) {
        int r0 = rowBase + wm + mt * 16 + (lane >> 2);
        float x2a = g_x2[r0];
        float x2b = g_x2[r0 + 8];
#pragma unroll
        for (int nt = 0; nt < 4; ++nt) {
            int cc = wn + nt * 8 + (lane & 3) * 2;
            float y2a = g_y2[cc], y2b = g_y2[cc + 1];
            float o[4];
#pragma unroll
            for (int q = 0; q < 4; ++q) {
                float xy = acc[mt][nt][q];
                float x2 = (q < 2) ? x2a : x2b;
                float y2 = (q & 1) ? y2b : y2a;
                float sq  = x2 + y2 - 2.0f * xy;
                float den = fmaf(x2, y2, 1.0f - 2.0f * xy);
                if (sq >= CLIPMAX * den) {
                    o[q] = dclip;
                } else if (sq <= 0.0f) {
                    o[q] = 0.0f;
                } else {
                    float s = sqrtf(__fdividef(sq, den));
                    o[q] = -__logf(__fdividef(1.0f + s, 1.0f - s));
                }
            }
            *(float2*)&logits[(size_t)r0 * L_DIM + cc]       = make_float2(o[0], o[1]);
            *(float2*)&logits[(size_t)(r0 + 8) * L_DIM + cc] = make_float2(o[2], o[3]);
        }
    }
}

// ---------------------------------------------------------------------------
extern "C" void kernel_launch(void* const* d_in, const int* in_sizes, int n_in,
                              void* d_out, int out_size)
{
    const float* cls  = (const float*)d_in[0];   // [B, 768]
    const float* Wm   = (const float*)d_in[1];   // [768, 384]
    const float* bias = (const float*)d_in[2];   // [384]
    const float* Y    = (const float*)d_in[3];   // [128, 384]

    const int B = in_sizes[0] / H_DIM;

    float* out = (float*)d_out;
    float* logits = out;                          // [B, 128]
    float* x = out + (size_t)B * L_DIM;           // [B, 384]

    cudaFuncSetAttribute(gemm1_fused, cudaFuncAttributeMaxDynamicSharedMemorySize, G1_SMEM);
    cudaFuncSetAttribute(gemm2_mma, cudaFuncAttributeMaxDynamicSharedMemorySize, G2_SMEM);

    convert_A<<<(int)(((size_t)B * H_DIM / 8) / 256), 256>>>(cls);
    transpose_w_h<<<dim3(H_DIM / 32, D_DIM / 32), dim3(32, 8)>>>(Wm);
    convert_Y<<<L_DIM / 8, 256>>>(Y);
    gemm1_fused<<<B / 128, 512, G1_SMEM>>>(bias, x);
    gemm2_mma<<<B / 128, 256, G2_SMEM>>>(logits);
}

// round 16
// speedup vs baseline: 1.0525x; 1.0525x over previous
#include <cuda_runtime.h>
#include <cuda_fp16.h>
#include <math.h>
#include <cstdint>

#define H_DIM 768
#define D_DIM 384
#define L_DIM 128
#define B_MAX 32768

// -------- scratch (module globals; no runtime allocation) --------
__device__ float  g_x2[B_MAX];
__device__ float  g_scale[B_MAX];
__device__ float  g_y2[L_DIM];
__device__ __half g_Ah[(size_t)B_MAX * H_DIM];   // cls in fp16
__device__ __half g_Xh[(size_t)B_MAX * D_DIM];   // projected p in fp16 (UNscaled)
__device__ __half g_Wth[(size_t)D_DIM * H_DIM];  // W^T in fp16 [D][H]
__device__ __half g_Yh[(size_t)L_DIM * D_DIM];   // Y in fp16 [L][D]

// ---------------- helpers ----------------
__device__ __forceinline__ uint32_t smem_u32(const void* p) {
    uint32_t a;
    asm("{ .reg .u64 t; cvta.to.shared.u64 t, %1; cvt.u32.u64 %0, t; }" : "=r"(a) : "l"(p));
    return a;
}
__device__ __forceinline__ void cp_async16(uint32_t s, const void* g) {
    asm volatile("cp.async.cg.shared.global [%0], [%1], 16;" :: "r"(s), "l"(g));
}
#define CP_COMMIT asm volatile("cp.async.commit_group;" ::: "memory")
#define CP_WAIT1  asm volatile("cp.async.wait_group 1;" ::: "memory")
#define CP_WAIT0  asm volatile("cp.async.wait_group 0;" ::: "memory")
#define CP_WAIT2  asm volatile("cp.async.wait_group 2;" ::: "memory")

__device__ __forceinline__ void mma_fp16(float* d, const uint32_t* a, const uint32_t* b) {
    asm volatile(
        "mma.sync.aligned.m16n8k16.row.col.f32.f16.f16.f32 "
        "{%0,%1,%2,%3}, {%4,%5,%6,%7}, {%8,%9}, {%0,%1,%2,%3};"
        : "+f"(d[0]), "+f"(d[1]), "+f"(d[2]), "+f"(d[3])
        : "r"(a[0]), "r"(a[1]), "r"(a[2]), "r"(a[3]), "r"(b[0]), "r"(b[1]));
}
__device__ __forceinline__ void ldsm_x4(uint32_t addr, uint32_t& r0, uint32_t& r1,
                                        uint32_t& r2, uint32_t& r3) {
    asm volatile("ldmatrix.sync.aligned.m8n8.x4.shared.b16 {%0,%1,%2,%3}, [%4];"
                 : "=r"(r0), "=r"(r1), "=r"(r2), "=r"(r3) : "r"(addr));
}

#define ASTR 72                             // 64 k-halves + 8 pad (144B rows)

// ========== GEMM1: CTA 128x192, warp 64x48, 8 warps, 2-stage k64 ==========
#define G1_A_HALVES (128 * ASTR)
#define G1_A_BYTES  (G1_A_HALVES * 2)       // 18432
#define G1_B_HALVES (192 * ASTR)
#define G1_STAGE_HALVES (G1_A_HALVES + G1_B_HALVES)
#define G1_STAGE_BYTES  (G1_STAGE_HALVES * 2)   // 46080
#define G1_SMEM     (2 * G1_STAGE_BYTES)        // 92160 -> 2 CTAs/SM

__device__ __forceinline__ void g1_stage(uint32_t sstage, const __half* Ag,
                                         const __half* Bg, int tid) {
#pragma unroll
    for (int i = 0; i < 4; ++i) {           // A: 128x64
        int idx = i * 256 + tid;
        int row = idx >> 3, k8 = idx & 7;
        cp_async16(sstage + (uint32_t)((row * ASTR + k8 * 8) * 2),
                   Ag + (size_t)row * H_DIM + k8 * 8);
    }
#pragma unroll
    for (int i = 0; i < 6; ++i) {           // B: 192x64
        int idx = i * 256 + tid;
        int row = idx >> 3, k8 = idx & 7;
        cp_async16(sstage + (uint32_t)(G1_A_BYTES + (row * ASTR + k8 * 8) * 2),
                   Bg + (size_t)row * H_DIM + k8 * 8);
    }
}

// one k64 chunk: 4 k16 steps, warp tile 64x48 (4 A-ldsm + 3 B-ldsm + 24 mma)
__device__ __forceinline__ void g1_compute_chunk(uint32_t sA, uint32_t sB,
                                                 int wm, int wn, int lane,
                                                 float acc[4][6][4]) {
    const int il = lane & 7, g = lane >> 3;
#pragma unroll
    for (int s = 0; s < 4; ++s) {
        const int kb = s * 16;
        uint32_t af[4][4], bf[6][2];
        uint32_t aoff = (uint32_t)(((wm + (g & 1) * 8 + il) * ASTR + kb + (g >> 1) * 8) * 2);
#pragma unroll
        for (int mt = 0; mt < 4; ++mt)
            ldsm_x4(sA + aoff + mt * (16 * ASTR * 2),
                    af[mt][0], af[mt][1], af[mt][2], af[mt][3]);
        uint32_t boff = (uint32_t)(((wn + (g >> 1) * 8 + il) * ASTR + kb + (g & 1) * 8) * 2);
#pragma unroll
        for (int np = 0; np < 3; ++np)
            ldsm_x4(sB + boff + np * (16 * ASTR * 2),
                    bf[np * 2][0], bf[np * 2][1], bf[np * 2 + 1][0], bf[np * 2 + 1][1]);
#pragma unroll
        for (int mt = 0; mt < 4; ++mt)
#pragma unroll
            for (int nt = 0; nt < 6; ++nt)
                mma_fp16(acc[mt][nt], af[mt], bf[nt]);
    }
}

__global__ __launch_bounds__(256, 2)
void gemm1_mma(const float* __restrict__ bias)
{
    extern __shared__ __half smh[];
    const uint32_t sb = smem_u32(smh);
    const int tid = threadIdx.x, lane = tid & 31, warp = tid >> 5;
    const int wm = (warp >> 2) * 64, wn = (warp & 3) * 48;
    const int rowBase = blockIdx.y * 128, colBase = blockIdx.x * 192;

    const __half* Abase = g_Ah + (size_t)rowBase * H_DIM;
    const __half* Bbase = g_Wth + (size_t)colBase * H_DIM;

    float acc[4][6][4];
#pragma unroll
    for (int mt = 0; mt < 4; ++mt)
#pragma unroll
        for (int nt = 0; nt < 6; ++nt)
#pragma unroll
            for (int q = 0; q < 4; ++q) acc[mt][nt][q] = 0.f;

    const int NCH = H_DIM / 64;   // 12
    g1_stage(sb, Abase, Bbase, tid);
    CP_COMMIT;
    g1_stage(sb + G1_STAGE_BYTES, Abase + 64, Bbase + 64, tid);
    CP_COMMIT;

#pragma unroll 1
    for (int c = 0; c < NCH; ++c) {
        if (c == NCH - 1) { CP_WAIT0; } else { CP_WAIT1; }
        __syncthreads();
        const uint32_t sA = sb + (c & 1) * G1_STAGE_BYTES;
        g1_compute_chunk(sA, sA + G1_A_BYTES, wm, wn, lane, acc);
        if (c + 2 < NCH) {
            __syncthreads();
            g1_stage(sb + (c & 1) * G1_STAGE_BYTES,
                     Abase + (c + 2) * 64, Bbase + (c + 2) * 64, tid);
            CP_COMMIT;
        }
    }

    // epilogue: bias add, write p as fp16 to g_Xh (UNscaled)
#pragma unroll
    for (int mt = 0; mt < 4; ++mt) {
        int r0 = rowBase + wm + mt * 16 + (lane >> 2);
#pragma unroll
        for (int nt = 0; nt < 6; ++nt) {
            int cc = colBase + wn + nt * 8 + (lane & 3) * 2;
            float b0 = bias[cc], b1 = bias[cc + 1];
            __half2 h0 = __floats2half2_rn(acc[mt][nt][0] + b0, acc[mt][nt][1] + b1);
            __half2 h1 = __floats2half2_rn(acc[mt][nt][2] + b0, acc[mt][nt][3] + b1);
            *(uint32_t*)&g_Xh[(size_t)r0 * D_DIM + cc]       = *(uint32_t*)&h0;
            *(uint32_t*)&g_Xh[(size_t)(r0 + 8) * D_DIM + cc] = *(uint32_t*)&h1;
        }
    }
}

// ========== GEMM2: 128x128 tile, warp 64x32, fused distance ==========
#define A_HALVES (128 * ASTR)
#define A_BYTES  (A_HALVES * 2)
#define STAGE_HALVES (A_HALVES + 128 * ASTR)
#define STAGE_BYTES  (STAGE_HALVES * 2)
#define NSTAGE 3
#define G2_SMEM   (NSTAGE * STAGE_BYTES)

__device__ __forceinline__ void stage_k64(uint32_t sstage, const __half* Ag,
                                          const __half* Bg, int ld, int tid) {
#pragma unroll
    for (int i = 0; i < 4; ++i) {
        int idx = i * 256 + tid;
        int row = idx >> 3, k8 = idx & 7;
        cp_async16(sstage + (uint32_t)((row * ASTR + k8 * 8) * 2),
                   Ag + (size_t)row * ld + k8 * 8);
    }
#pragma unroll
    for (int i = 0; i < 4; ++i) {
        int idx = i * 256 + tid;
        int row = idx >> 3, k8 = idx & 7;
        cp_async16(sstage + (uint32_t)(A_BYTES + (row * ASTR + k8 * 8) * 2),
                   Bg + (size_t)row * ld + k8 * 8);
    }
}

__device__ __forceinline__ void load_frags(uint32_t sA, uint32_t sB, int kb,
                                           int wm, int wn, int lane,
                                           uint32_t af[4][4], uint32_t bf[4][2]) {
    const int il = lane & 7, g = lane >> 3;
    uint32_t aoff = (uint32_t)(((wm + (g & 1) * 8 + il) * ASTR + kb + (g >> 1) * 8) * 2);
#pragma unroll
    for (int mt = 0; mt < 4; ++mt)
        ldsm_x4(sA + aoff + mt * (16 * ASTR * 2),
                af[mt][0], af[mt][1], af[mt][2], af[mt][3]);
    uint32_t boff = (uint32_t)(((wn + (g >> 1) * 8 + il) * ASTR + kb + (g & 1) * 8) * 2);
#pragma unroll
    for (int np = 0; np < 2; ++np)
        ldsm_x4(sB + boff + np * (16 * ASTR * 2),
                bf[np * 2][0], bf[np * 2][1], bf[np * 2 + 1][0], bf[np * 2 + 1][1]);
}
__device__ __forceinline__ void mma_all(uint32_t af[4][4], uint32_t bf[4][2],
                                        float acc[4][4][4]) {
#pragma unroll
    for (int mt = 0; mt < 4; ++mt)
#pragma unroll
        for (int nt = 0; nt < 4; ++nt)
            mma_fp16(acc[mt][nt], af[mt], bf[nt]);
}
__device__ __forceinline__ void compute_chunk(uint32_t sA, uint32_t sB,
                                              int wm, int wn, int lane,
                                              float acc[4][4][4]) {
    uint32_t af[2][4][4], bf[2][4][2];
    load_frags(sA, sB, 0, wm, wn, lane, af[0], bf[0]);
#pragma unroll
    for (int s = 0; s < 4; ++s) {
        if (s < 3)
            load_frags(sA, sB, (s + 1) * 16, wm, wn, lane, af[(s + 1) & 1], bf[(s + 1) & 1]);
        mma_all(af[s & 1], bf[s & 1], acc);
    }
}

// ---------------- conversion kernels ----------------
__global__ void convert_A(const float* __restrict__ A) {
    size_t i = (size_t)blockIdx.x * blockDim.x + threadIdx.x;
    const float4 v0 = ((const float4*)A)[i * 2];
    const float4 v1 = ((const float4*)A)[i * 2 + 1];
    __half2 h0 = __floats2half2_rn(v0.x, v0.y);
    __half2 h1 = __floats2half2_rn(v0.z, v0.w);
    __half2 h2 = __floats2half2_rn(v1.x, v1.y);
    __half2 h3 = __floats2half2_rn(v1.z, v1.w);
    uint4 u;
    u.x = *(uint32_t*)&h0; u.y = *(uint32_t*)&h1;
    u.z = *(uint32_t*)&h2; u.w = *(uint32_t*)&h3;
    ((uint4*)g_Ah)[i] = u;
}

__global__ void transpose_w_h(const float* __restrict__ W) {
    __shared__ float t[32][33];
    int bx = blockIdx.x * 32;
    int by = blockIdx.y * 32;
    int x = threadIdx.x, y = threadIdx.y;
#pragma unroll
    for (int i = 0; i < 32; i += 8)
        t[y + i][x] = W[(size_t)(bx + y + i) * D_DIM + by + x];
    __syncthreads();
#pragma unroll
    for (int i = 0; i < 32; i += 8)
        g_Wth[(size_t)(by + y + i) * H_DIM + bx + x] = __float2half_rn(t[x][y + i]);
}

__global__ __launch_bounds__(256)
void convert_Y(const float* __restrict__ Y) {
    const int warp = threadIdx.x >> 5, lane = threadIdx.x & 31;
    const int row = blockIdx.x * 8 + warp;
    const float* y = Y + (size_t)row * D_DIM;
    __half* yh = g_Yh + (size_t)row * D_DIM;
    float s = 0.f;
#pragma unroll
    for (int j = 0; j < 3; ++j) {
        float4 v = ((const float4*)y)[j * 32 + lane];
        s += v.x * v.x + v.y * v.y + v.z * v.z + v.w * v.w;
        __half2 h0 = __floats2half2_rn(v.x, v.y);
        __half2 h1 = __floats2half2_rn(v.z, v.w);
        uint2 u; u.x = *(uint32_t*)&h0; u.y = *(uint32_t*)&h1;
        ((uint2*)yh)[j * 32 + lane] = u;
    }
#pragma unroll
    for (int o = 16; o > 0; o >>= 1) s += __shfl_xor_sync(0xFFFFFFFFu, s, o);
    if (lane == 0) g_y2[row] = s;
}

// ---------------- finish_rows: read p (fp16), write x (fp32) + x2 + scale ----
__global__ __launch_bounds__(256)
void finish_rows(float* __restrict__ X) {
    const int warp = threadIdx.x >> 5, lane = threadIdx.x & 31;
    const int row = blockIdx.x * 8 + warp;
    const __half* ph = g_Xh + (size_t)row * D_DIM;
    float* xp = X + (size_t)row * D_DIM;

    float2 pv[3][2];   // 12 floats per lane (vals of 2 half2 per j)
    float s = 0.f;
#pragma unroll
    for (int j = 0; j < 3; ++j) {
        uint2 u = ((const uint2*)ph)[j * 32 + lane];
        __half2 h0 = *(__half2*)&u.x;
        __half2 h1 = *(__half2*)&u.y;
        float2 f0 = __half22float2(h0);
        float2 f1 = __half22float2(h1);
        pv[j][0] = f0; pv[j][1] = f1;
        s += f0.x * f0.x + f0.y * f0.y + f1.x * f1.x + f1.y * f1.y;
    }
#pragma unroll
    for (int o = 16; o > 0; o >>= 1) s += __shfl_xor_sync(0xFFFFFFFFu, s, o);

    float nsq = s;
    float n = fmaxf(sqrtf(nsq), 1e-15f);
    float scale = tanhf(n) / n;
    if (lane == 0) {
        g_x2[row] = nsq * scale * scale;
        g_scale[row] = scale;
    }

#pragma unroll
    for (int j = 0; j < 3; ++j) {
        float4 w;
        w.x = pv[j][0].x * scale; w.y = pv[j][0].y * scale;
        w.z = pv[j][1].x * scale; w.w = pv[j][1].y * scale;
        ((float4*)xp)[j * 32 + lane] = w;
    }
}

// ---------------- GEMM2: xy = scale_r * (p @ Y^T), fused Poincare distance --
__global__ __launch_bounds__(256, 2)
void gemm2_mma(float* __restrict__ logits)
{
    extern __shared__ __half smh[];
    const uint32_t sb = smem_u32(smh);
    const int tid = threadIdx.x, lane = tid & 31, warp = tid >> 5;
    const int wm = (warp >> 2) * 64, wn = (warp & 3) * 32;
    const int rowBase = blockIdx.x * 128;

    const __half* Abase = g_Xh + (size_t)rowBase * D_DIM;   // unscaled p
    const __half* Bbase = g_Yh;

    float acc[4][4][4];
#pragma unroll
    for (int mt = 0; mt < 4; ++mt)
#pragma unroll
        for (int nt = 0; nt < 4; ++nt)
#pragma unroll
            for (int q = 0; q < 4; ++q) acc[mt][nt][q] = 0.f;

    const int NCH = D_DIM / 64;   // 6
#pragma unroll
    for (int s = 0; s < NSTAGE - 1; ++s) {
        stage_k64(sb + s * STAGE_BYTES, Abase + s * 64, Bbase + s * 64, D_DIM, tid);
        CP_COMMIT;
    }

#pragma unroll 1
    for (int c = 0; c < NCH; ++c) {
        if (c + NSTAGE - 1 < NCH) {
            stage_k64(sb + ((c + NSTAGE - 1) % NSTAGE) * STAGE_BYTES,
                      Abase + (c + NSTAGE - 1) * 64, Bbase + (c + NSTAGE - 1) * 64,
                      D_DIM, tid);
        }
        CP_COMMIT;
        CP_WAIT2;
        __syncthreads();
        const uint32_t sA = sb + (c % NSTAGE) * STAGE_BYTES;
        compute_chunk(sA, sA + A_BYTES, wm, wn, lane, acc);
        __syncthreads();
    }

    const float CLIPMAX = (1.0f - 1e-5f) * (1.0f - 1e-5f);
    const float sclip = sqrtf(CLIPMAX);
    const float dclip = -__logf(__fdividef(1.0f + sclip, 1.0f - sclip));

#pragma unroll
    for (int mt = 0; mt < 4; ++mt) {
        int r0 = rowBase + wm + mt * 16 + (lane >> 2);
        float x2a = g_x2[r0];
        float x2b = g_x2[r0 + 8];
        float sca = g_scale[r0];
        float scb = g_scale[r0 + 8];
#pragma unroll
        for (int nt = 0; nt < 4; ++nt) {
            int cc = wn + nt * 8 + (lane & 3) * 2;
            float y2a = g_y2[cc], y2b = g_y2[cc + 1];
            float o[4];
#pragma unroll
            for (int q = 0; q < 4; ++q) {
                float xy = acc[mt][nt][q] * ((q < 2) ? sca : scb);
                float x2 = (q < 2) ? x2a : x2b;
                float y2 = (q & 1) ? y2b : y2a;
                float sq  = x2 + y2 - 2.0f * xy;
                float den = fmaf(x2, y2, 1.0f - 2.0f * xy);
                if (sq >= CLIPMAX * den) {
                    o[q] = dclip;
                } else if (sq <= 0.0f) {
                    o[q] = 0.0f;
                } else {
                    float s = sqrtf(__fdividef(sq, den));
                    o[q] = -__logf(__fdividef(1.0f + s, 1.0f - s));
                }
            }
            *(float2*)&logits[(size_t)r0 * L_DIM + cc]       = make_float2(o[0], o[1]);
            *(float2*)&logits[(size_t)(r0 + 8) * L_DIM + cc] = make_float2(o[2], o[3]);
        }
    }
}

// ---------------------------------------------------------------------------
extern "C" void kernel_launch(void* const* d_in, const int* in_sizes, int n_in,
                              void* d_out, int out_size)
{
    const float* cls  = (const float*)d_in[0];   // [B, 768]
    const float* Wm   = (const float*)d_in[1];   // [768, 384]
    const float* bias = (const float*)d_in[2];   // [384]
    const float* Y    = (const float*)d_in[3];   // [128, 384]

    const int B = in_sizes[0] / H_DIM;

    float* out = (float*)d_out;
    float* logits = out;                          // [B, 128]
    float* x = out + (size_t)B * L_DIM;           // [B, 384]

    cudaFuncSetAttribute(gemm1_mma, cudaFuncAttributeMaxDynamicSharedMemorySize, G1_SMEM);
    cudaFuncSetAttribute(gemm2_mma, cudaFuncAttributeMaxDynamicSharedMemorySize, G2_SMEM);

    convert_A<<<(int)(((size_t)B * H_DIM / 8) / 256), 256>>>(cls);
    transpose_w_h<<<dim3(H_DIM / 32, D_DIM / 32), dim3(32, 8)>>>(Wm);
    convert_Y<<<L_DIM / 8, 256>>>(Y);
    gemm1_mma<<<dim3(D_DIM / 192, B / 128), 256, G1_SMEM>>>(bias);
    finish_rows<<<B / 8, 256>>>(x);
    gemm2_mma<<<B / 128, 256, G2_SMEM>>>(logits);
}